// round 9
// baseline (speedup 1.0000x reference)
#include <cuda_runtime.h>
#include <cstdint>

#define Hc 128
#define Nc 128
#define Lc 2048

typedef unsigned long long ull;

// Scratch for synthesized kernel Kl[h,l]  (1 MB)
__device__ float g_Kl[Hc * Lc];

// ---------------------------------------------------------------------------
__device__ __forceinline__ void ffma2(ull& acc, ull a, ull b) {
    asm("fma.rn.f32x2 %0, %1, %2, %0;" : "+l"(acc) : "l"(a), "l"(b));
}
__device__ __forceinline__ ull pack2(float lo, float hi) {
    ull r;
    asm("mov.b64 %0, {%1, %2};" : "=l"(r) : "f"(lo), "f"(hi));
    return r;
}
__device__ __forceinline__ float addpair(ull v) {
    float a, b;
    asm("mov.b64 {%0,%1}, %2;" : "=f"(a), "=f"(b) : "l"(v));
    return a + b;
}
__device__ __forceinline__ float lo32(ull v) {
    float a, b;
    asm("mov.b64 {%0,%1}, %2;" : "=f"(a), "=f"(b) : "l"(v));
    return a;
}

// ---------------------------------------------------------------------------
// Kernel 1: Kl[h,l] = sum_n C[h,n] * K[l,h,n]
// 512 blocks x 4 l-slabs (256KB contiguous per block). Warp reads 16
// consecutive h-rows per l (MLP=16, streaming). Results buffered in smem,
// stored as coalesced float2 tiles.
// ---------------------------------------------------------------------------
__global__ __launch_bounds__(256) void kl_synth_kernel(
    const float* __restrict__ K,   // (L,H,N)
    const float* __restrict__ C)   // (H,N)
{
    __shared__ float sKl[Hc * 4];      // [h][ls] tile, 2KB

    const int l0   = blockIdx.x * 4;
    const int warp = threadIdx.x >> 5;
    const int lane = threadIdx.x & 31;
    const int h0   = warp * 16;

    #pragma unroll 1
    for (int ls = 0; ls < 4; ++ls) {
        const float4* Kl4 =
            reinterpret_cast<const float4*>(K + (size_t)(l0 + ls) * (Hc * Nc));

        float4 kv[16];
        #pragma unroll
        for (int r = 0; r < 16; ++r)
            kv[r] = __ldcs(Kl4 + (h0 + r) * (Nc / 4) + lane);

        float s[16];
        #pragma unroll
        for (int r = 0; r < 16; ++r) {
            const float4 c4 =
                reinterpret_cast<const float4*>(C + (h0 + r) * Nc)[lane];
            s[r] = c4.x * kv[r].x + c4.y * kv[r].y
                 + c4.z * kv[r].z + c4.w * kv[r].w;
        }
        #pragma unroll
        for (int r = 0; r < 16; ++r) {
            #pragma unroll
            for (int o = 16; o > 0; o >>= 1)
                s[r] += __shfl_xor_sync(0xFFFFFFFFu, s[r], o);
        }
        if (lane == 0) {
            #pragma unroll
            for (int r = 0; r < 16; ++r)
                sKl[(h0 + r) * 4 + ls] = s[r];
        }
    }
    __syncthreads();

    // coalesced store: row h -> 16B = 2 float2; threads 2h, 2h+1 cover it
    {
        const int h    = threadIdx.x >> 1;
        const int part = threadIdx.x & 1;
        float2 v = reinterpret_cast<const float2*>(sKl)[h * 2 + part];
        *reinterpret_cast<float2*>(g_Kl + h * Lc + l0 + part * 2) = v;
    }
}

// ---------------------------------------------------------------------------
// Kernel 2: depthwise 'same' conv + skip, packed f32x2.
// 512 threads: i = tid&127 owns outputs t in [16i,16i+16); q = tid>>7 owns
// m-chunks [16q, 16q+16). Same verified pairing identity as R3-R5:
//   even t: k2e[p]={k[2p+1],k[2p]} * u2[F],  F = 8i+j+1023-p
//   odd  t: k2o[p]={k[2p],k[2p-1]} * u2[F+1], fixup m=2047 on odd outputs.
// Quarters accumulate SEQUENTIALLY into one ybuf (fits 48KB static smem).
// Static smem total: 20 + 8 + 8 + 8 = 44 KB.
// ---------------------------------------------------------------------------
__global__ __launch_bounds__(512) void conv_kernel(
    const float* __restrict__ u,   // (H,L)
    const float* __restrict__ D,   // (H,)
    float* __restrict__ y)         // (H,L)
{
    __shared__ ulonglong2 suq[1280];   // skewed float4 u blocks (20.0 KB)
    __shared__ ull k2e[1024];          // 8 KB
    __shared__ ull k2o[1024];          // 8 KB
    __shared__ float ybuf[Lc];         // 8 KB

    const int h   = blockIdx.x;
    const int tid = threadIdx.x;

    // ---- build swapped k-pair tables ----
    const float* kl = g_Kl + h * Lc;
    for (int p = tid; p < 1024; p += 512) {
        float ke = kl[2 * p];
        float ko = kl[2 * p + 1];
        k2e[p] = pack2(ko, ke);                        // {k[2p+1], k[2p]}
        k2o[p] = pack2(ke, p ? kl[2 * p - 1] : 0.0f);  // {k[2p],  k[2p-1]}
    }

    // ---- fill skewed padded u (valid a in [1024, 3072)) ----
    const float4* ug4 = reinterpret_cast<const float4*>(u + h * Lc);
    for (int Q = tid; Q < 1024; Q += 512) {
        float4 v = make_float4(0.f, 0.f, 0.f, 0.f);
        if (Q >= 256 && Q < 768) v = ug4[Q - 256];
        ulonglong2 w;
        w.x = pack2(v.x, v.y);
        w.y = pack2(v.z, v.w);
        suq[Q + (Q >> 2)] = w;
    }
    __syncthreads();

    const int i = tid & 127;           // output tile
    const int q = tid >> 7;            // m-quarter: chunks [16q, 16q+16)

    ull accE[8], accO[8];
    #pragma unroll
    for (int j = 0; j < 8; ++j) { accE[j] = 0ULL; accO[j] = 0ULL; }

    int Q0 = 4 * i + 504 - 128 * q;    // Q0 = 4i + 504 - 8c at c = 16q
    const int pbase = 256 * q;

    #pragma unroll 1
    for (int cc = 0; cc < 16; ++cc) {
        ull W[24];
        const int base = Q0 + (Q0 >> 2);   // Q0 multiple of 4 -> exact skew
        #pragma unroll
        for (int b = 0; b < 12; ++b) {
            ulonglong2 v = suq[base + b + (b >> 2)];
            W[2 * b]     = v.x;
            W[2 * b + 1] = v.y;
        }
        const int p0 = pbase + 16 * cc;
        #pragma unroll
        for (int dp = 0; dp < 16; ++dp) {
            const ull kve = k2e[p0 + dp];
            #pragma unroll
            for (int j = 0; j < 8; ++j)
                ffma2(accE[j], kve, W[15 - dp + j]);
            const ull kvo = k2o[p0 + dp];
            #pragma unroll
            for (int j = 0; j < 8; ++j)
                ffma2(accO[j], kvo, W[16 - dp + j]);
        }
        Q0 -= 8;
    }

    // ---- sequential quarter accumulation into single ybuf ----
    const float* suf = reinterpret_cast<const float*>(suq);

    if (q == 0) {
        const float dh = D[h];   // fold skip connection into q0's write
        #pragma unroll
        for (int j = 0; j < 8; ++j) {
            const int tE = 16 * i + 2 * j;
            const int tO = tE + 1;
            int aE = tE + 1024, QE = aE >> 2;
            int aO = tO + 1024, QO = aO >> 2;
            float uE = suf[(QE + (QE >> 2)) * 4 + (aE & 3)];
            float uO = suf[(QO + (QO >> 2)) * 4 + (aO & 3)];
            ybuf[tE] = addpair(accE[j]) + dh * uE;
            ybuf[tO] = addpair(accO[j]) + dh * uO;
        }
    }
    __syncthreads();
    if (q == 1) {
        #pragma unroll
        for (int j = 0; j < 8; ++j) {
            const int tE = 16 * i + 2 * j;
            ybuf[tE]     += addpair(accE[j]);
            ybuf[tE + 1] += addpair(accO[j]);
        }
    }
    __syncthreads();
    if (q == 2) {
        #pragma unroll
        for (int j = 0; j < 8; ++j) {
            const int tE = 16 * i + 2 * j;
            ybuf[tE]     += addpair(accE[j]);
            ybuf[tE + 1] += addpair(accO[j]);
        }
    }
    __syncthreads();
    if (q == 3) {
        const float k2047 = lo32(k2e[1023]);   // k[2047]
        #pragma unroll
        for (int j = 0; j < 8; ++j) {
            const int tE = 16 * i + 2 * j;
            const int tO = tE + 1;
            ybuf[tE] += addpair(accE[j]);
            // fixup m = 2047 (odd outputs): u[tO - 1024] -> a = tO
            int a = tO, Q = a >> 2;
            ybuf[tO] += addpair(accO[j])
                      + k2047 * suf[(Q + (Q >> 2)) * 4 + (a & 3)];
        }
    }
    __syncthreads();

    // ---- coalesced store (512 float4 = 2048 floats) ----
    reinterpret_cast<float4*>(y + h * Lc)[tid] =
        reinterpret_cast<const float4*>(ybuf)[tid];
}

// ---------------------------------------------------------------------------
extern "C" void kernel_launch(void* const* d_in, const int* in_sizes, int n_in,
                              void* d_out, int out_size)
{
    const float* u = nullptr;
    const float* C = nullptr;
    const float* D = nullptr;
    const float* K = nullptr;
    for (int i = 0; i < n_in; ++i) {
        switch (in_sizes[i]) {
            case Hc * Lc:  u = (const float*)d_in[i]; break;
            case Hc * Nc:  C = (const float*)d_in[i]; break;
            case Hc:       D = (const float*)d_in[i]; break;
            default:
                if (in_sizes[i] == Lc * Hc * Nc) K = (const float*)d_in[i];
                break;
        }
    }

    float* y = (float*)d_out;

    kl_synth_kernel<<<Lc / 4, 256>>>(K, C);   // 512 blocks x 4 contiguous slabs
    conv_kernel<<<Hc, 512>>>(u, D, y);
}

// round 10
// speedup vs baseline: 1.0350x; 1.0350x over previous
#include <cuda_runtime.h>
#include <cstdint>

#define Hc 128
#define Nc 128
#define Lc 2048

typedef unsigned long long ull;

// ---------------------------------------------------------------------------
__device__ __forceinline__ void ffma2(ull& acc, ull a, ull b) {
    asm("fma.rn.f32x2 %0, %1, %2, %0;" : "+l"(acc) : "l"(a), "l"(b));
}
__device__ __forceinline__ ull pack2(float lo, float hi) {
    ull r;
    asm("mov.b64 %0, {%1, %2};" : "=l"(r) : "f"(lo), "f"(hi));
    return r;
}
__device__ __forceinline__ float addpair(ull v) {
    float a, b;
    asm("mov.b64 {%0,%1}, %2;" : "=f"(a), "=f"(b) : "l"(v));
    return a + b;
}
__device__ __forceinline__ float lo32(ull v) {
    float a, b;
    asm("mov.b64 {%0,%1}, %2;" : "=f"(a), "=f"(b) : "l"(v));
    return a;
}

// ---------------------------------------------------------------------------
// FUSED kernel: one block per channel h.
//   Stage s (16 stages, slab = 128 l-values):
//     - issue LDG for K slab s+1 (held in registers, latency hidden by conv)
//     - conv m-chunk c = 4s + q per thread-quarter (pair tables of slab s)
//     - dot kv with C[h], shfl-reduce -> k values of slab s+1 -> pair tables
// Conv identity (verified rel_err ~3e-7 since R3):
//   even t: k2e[p]={k[2p+1],k[2p]} * u2[F],   F = 8i+j+1023-p
//   odd  t: k2o[p]={k[2p],k[2p-1]} * u2[F+1]; fixup m=2047 on odd outputs.
// smem: suq 20KB + k2e 8KB + k2o 8KB + ybuf 8KB + sknew 0.5KB = ~44.6KB
// ---------------------------------------------------------------------------
__global__ __launch_bounds__(512, 1) void lssl_fused_kernel(
    const float* __restrict__ K,   // (L,H,N)
    const float* __restrict__ C,   // (H,N)
    const float* __restrict__ u,   // (H,L)
    const float* __restrict__ D,   // (H,)
    float* __restrict__ y)         // (H,L)
{
    __shared__ ulonglong2 suq[1280];   // skewed float4 u blocks (20.0 KB)
    __shared__ ull k2e[1024];          // 8 KB
    __shared__ ull k2o[1024];          // 8 KB
    __shared__ float ybuf[Lc];         // 8 KB
    __shared__ float sknew[128];       // 0.5 KB: freshly synthesized k slab

    const int h    = blockIdx.x;
    const int tid  = threadIdx.x;
    const int warp = tid >> 5;
    const int lane = tid & 31;

    // C row for this channel: float4 per lane (constant for all dots)
    const float4 c4 = reinterpret_cast<const float4*>(C + h * Nc)[lane];

    // tid0-private boundary carry: k[128*sigma - 1]
    float kprev = 0.0f;

    // ---- issue loads for slab 0 (rows l = 8*warp + r) ----
    float4 kv[8];
    {
        #pragma unroll
        for (int r = 0; r < 8; ++r) {
            const int l = 8 * warp + r;
            kv[r] = __ldcs(reinterpret_cast<const float4*>(
                        K + ((size_t)l * Hc + h) * Nc) + lane);
        }
    }

    // ---- fill skewed padded u (valid a in [1024, 3072)) ----
    const float4* ug4 = reinterpret_cast<const float4*>(u + h * Lc);
    for (int Q = tid; Q < 1024; Q += 512) {
        float4 v = make_float4(0.f, 0.f, 0.f, 0.f);
        if (Q >= 256 && Q < 768) v = ug4[Q - 256];
        ulonglong2 w;
        w.x = pack2(v.x, v.y);
        w.y = pack2(v.z, v.w);
        suq[Q + (Q >> 2)] = w;
    }

    // ---- synthesize slab 0 ----
    {
        float s[8];
        #pragma unroll
        for (int r = 0; r < 8; ++r)
            s[r] = c4.x * kv[r].x + c4.y * kv[r].y
                 + c4.z * kv[r].z + c4.w * kv[r].w;
        #pragma unroll
        for (int r = 0; r < 8; ++r) {
            #pragma unroll
            for (int o = 16; o > 0; o >>= 1)
                s[r] += __shfl_xor_sync(0xFFFFFFFFu, s[r], o);
        }
        if (lane == 0) {
            #pragma unroll
            for (int r = 0; r < 8; ++r) sknew[8 * warp + r] = s[r];
        }
    }
    __syncthreads();                       // suq + sknew(slab 0) visible
    if (tid < 64) {
        const int p2 = 2 * tid;
        const float klo = sknew[p2];       // k[2p]
        const float khi = sknew[p2 + 1];   // k[2p+1]
        k2e[tid] = pack2(khi, klo);
        k2o[tid] = pack2(klo, tid ? sknew[p2 - 1] : kprev);
    }
    if (tid == 0) kprev = sknew[127];
    __syncthreads();                       // pair tables slab 0 ready

    // ---- main pipelined loop ----
    const int i = tid & 127;               // output tile: t in [16i, 16i+16)
    const int q = tid >> 7;                // quarter

    ull accE[8], accO[8];
    #pragma unroll
    for (int j = 0; j < 8; ++j) { accE[j] = 0ULL; accO[j] = 0ULL; }

    #pragma unroll 1
    for (int s = 0; s < 16; ++s) {
        // 1. issue loads for slab s+1
        if (s < 15) {
            const int L0 = 128 * (s + 1);
            #pragma unroll
            for (int r = 0; r < 8; ++r) {
                const int l = L0 + 8 * warp + r;
                kv[r] = __ldcs(reinterpret_cast<const float4*>(
                            K + ((size_t)l * Hc + h) * Nc) + lane);
            }
        }

        // 2. conv chunk c = 4s + q  (pair tables of slab s)
        {
            const int c  = 4 * s + q;
            const int Q0 = 4 * i + 504 - 8 * c;
            const int p0 = 16 * c;
            ull W[24];
            const int base = Q0 + (Q0 >> 2);   // Q0 multiple of 4 -> exact
            #pragma unroll
            for (int b = 0; b < 12; ++b) {
                ulonglong2 v = suq[base + b + (b >> 2)];
                W[2 * b]     = v.x;
                W[2 * b + 1] = v.y;
            }
            #pragma unroll
            for (int dp = 0; dp < 16; ++dp) {
                const ull kve = k2e[p0 + dp];
                #pragma unroll
                for (int j = 0; j < 8; ++j)
                    ffma2(accE[j], kve, W[15 - dp + j]);
                const ull kvo = k2o[p0 + dp];
                #pragma unroll
                for (int j = 0; j < 8; ++j)
                    ffma2(accO[j], kvo, W[16 - dp + j]);
            }
        }

        // 3. synthesize slab s+1 and build its pair tables
        if (s < 15) {
            float sv[8];
            #pragma unroll
            for (int r = 0; r < 8; ++r)
                sv[r] = c4.x * kv[r].x + c4.y * kv[r].y
                      + c4.z * kv[r].z + c4.w * kv[r].w;
            #pragma unroll
            for (int r = 0; r < 8; ++r) {
                #pragma unroll
                for (int o = 16; o > 0; o >>= 1)
                    sv[r] += __shfl_xor_sync(0xFFFFFFFFu, sv[r], o);
            }
            if (lane == 0) {
                #pragma unroll
                for (int r = 0; r < 8; ++r) sknew[8 * warp + r] = sv[r];
            }
            __syncthreads();               // sknew(slab s+1) visible
            if (tid < 64) {
                const int pg = 64 * (s + 1) + tid;
                const int p2 = 2 * tid;
                const float klo = sknew[p2];
                const float khi = sknew[p2 + 1];
                k2e[pg] = pack2(khi, klo);
                k2o[pg] = pack2(klo, tid ? sknew[p2 - 1] : kprev);
            }
            if (tid == 0) kprev = sknew[127];
            __syncthreads();               // pair tables slab s+1 ready
        }
    }

    // ---- sequential quarter accumulation into ybuf ----
    const float* suf = reinterpret_cast<const float*>(suq);

    __syncthreads();
    if (q == 0) {
        const float dh = D[h];             // fold skip connection in
        #pragma unroll
        for (int j = 0; j < 8; ++j) {
            const int tE = 16 * i + 2 * j;
            const int tO = tE + 1;
            int aE = tE + 1024, QE = aE >> 2;
            int aO = tO + 1024, QO = aO >> 2;
            float uE = suf[(QE + (QE >> 2)) * 4 + (aE & 3)];
            float uO = suf[(QO + (QO >> 2)) * 4 + (aO & 3)];
            ybuf[tE] = addpair(accE[j]) + dh * uE;
            ybuf[tO] = addpair(accO[j]) + dh * uO;
        }
    }
    __syncthreads();
    if (q == 1) {
        #pragma unroll
        for (int j = 0; j < 8; ++j) {
            const int tE = 16 * i + 2 * j;
            ybuf[tE]     += addpair(accE[j]);
            ybuf[tE + 1] += addpair(accO[j]);
        }
    }
    __syncthreads();
    if (q == 2) {
        #pragma unroll
        for (int j = 0; j < 8; ++j) {
            const int tE = 16 * i + 2 * j;
            ybuf[tE]     += addpair(accE[j]);
            ybuf[tE + 1] += addpair(accO[j]);
        }
    }
    __syncthreads();
    if (q == 3) {
        const float k2047 = lo32(k2e[1023]);   // k[2047]
        #pragma unroll
        for (int j = 0; j < 8; ++j) {
            const int tE = 16 * i + 2 * j;
            const int tO = tE + 1;
            ybuf[tE] += addpair(accE[j]);
            // fixup m = 2047 (odd outputs): u[tO - 1024] -> a = tO
            int a = tO, Q = a >> 2;
            ybuf[tO] += addpair(accO[j])
                      + k2047 * suf[(Q + (Q >> 2)) * 4 + (a & 3)];
        }
    }
    __syncthreads();

    // ---- coalesced store (512 float4 = 2048 floats) ----
    reinterpret_cast<float4*>(y + h * Lc)[tid] =
        reinterpret_cast<const float4*>(ybuf)[tid];
}

// ---------------------------------------------------------------------------
extern "C" void kernel_launch(void* const* d_in, const int* in_sizes, int n_in,
                              void* d_out, int out_size)
{
    const float* u = nullptr;
    const float* C = nullptr;
    const float* D = nullptr;
    const float* K = nullptr;
    for (int i = 0; i < n_in; ++i) {
        switch (in_sizes[i]) {
            case Hc * Lc:  u = (const float*)d_in[i]; break;
            case Hc * Nc:  C = (const float*)d_in[i]; break;
            case Hc:       D = (const float*)d_in[i]; break;
            default:
                if (in_sizes[i] == Lc * Hc * Nc) K = (const float*)d_in[i];
                break;
        }
    }

    float* y = (float*)d_out;

    lssl_fused_kernel<<<Hc, 512>>>(K, C, u, D, y);
}

// round 13
// speedup vs baseline: 1.1009x; 1.0636x over previous
#include <cuda_runtime.h>
#include <cstdint>

#define Hc 128
#define Nc 128
#define Lc 2048

typedef unsigned long long ull;

// Transposed scratch: g_KlT[l * Hc + h] = Kl[h, l]   (1 MB)
__device__ float g_KlT[Lc * Hc];

// ---------------------------------------------------------------------------
__device__ __forceinline__ void ffma2(ull& acc, ull a, ull b) {
    asm("fma.rn.f32x2 %0, %1, %2, %0;" : "+l"(acc) : "l"(a), "l"(b));
}
__device__ __forceinline__ ull pack2(float lo, float hi) {
    ull r;
    asm("mov.b64 %0, {%1, %2};" : "=l"(r) : "f"(lo), "f"(hi));
    return r;
}
__device__ __forceinline__ float addpair(ull v) {
    float a, b;
    asm("mov.b64 {%0,%1}, %2;" : "=f"(a), "=f"(b) : "l"(v));
    return a + b;
}
__device__ __forceinline__ float lo32(ull v) {
    float a, b;
    asm("mov.b64 {%0,%1}, %2;" : "=f"(a), "=f"(b) : "l"(v));
    return a;
}

// ---------------------------------------------------------------------------
// Kernel 1: KlT[l,h] = sum_n C[h,n] * K[l,h,n]
// One block per l (grid 2048): K[l,:,:] is a contiguous 64KB slab.
// Warp reads 16 consecutive h-rows (8KB coalesced, MLP=16, streaming),
// shfl-reduces, stages results in smem, stores ONE contiguous 512B line.
// ---------------------------------------------------------------------------
__global__ __launch_bounds__(256) void kl_synth_kernel(
    const float* __restrict__ K,   // (L,H,N)
    const float* __restrict__ C)   // (H,N)
{
    __shared__ float sKl[Hc];          // 512B stage

    const int l    = blockIdx.x;
    const int warp = threadIdx.x >> 5;
    const int lane = threadIdx.x & 31;
    const int h0   = warp * 16;

    const float4* Kl4 = reinterpret_cast<const float4*>(K + (size_t)l * (Hc * Nc));

    float4 kv[16];
    #pragma unroll
    for (int r = 0; r < 16; ++r)
        kv[r] = __ldcs(Kl4 + (h0 + r) * (Nc / 4) + lane);

    float s[16];
    #pragma unroll
    for (int r = 0; r < 16; ++r) {
        const float4 c4 = reinterpret_cast<const float4*>(C + (h0 + r) * Nc)[lane];
        s[r] = c4.x * kv[r].x + c4.y * kv[r].y + c4.z * kv[r].z + c4.w * kv[r].w;
    }
    #pragma unroll
    for (int r = 0; r < 16; ++r) {
        #pragma unroll
        for (int o = 16; o > 0; o >>= 1)
            s[r] += __shfl_xor_sync(0xFFFFFFFFu, s[r], o);
    }
    if (lane == 0) {
        #pragma unroll
        for (int r = 0; r < 16; ++r) sKl[h0 + r] = s[r];
    }
    __syncthreads();

    if (threadIdx.x < 128)
        g_KlT[l * Hc + threadIdx.x] = sKl[threadIdx.x];
}

// ---------------------------------------------------------------------------
// Kernel 2: depthwise 'same' conv + skip, packed f32x2.
// 256-thread two-half structure — body verbatim from the R5-passing kernel
// (best measured conv: 31.1us); ONLY the k-table build changed to read the
// transposed KlT column h. Pairing identity (verified rel_err ~3e-7):
//   even t: k2e[p]={k[2p+1],k[2p]} * u2[F],   F = 8i+j+1023-p
//   odd  t: k2o[p]={k[2p],k[2p-1]} * u2[F+1]; fixup m=2047 on odd outputs.
// i = tid&127 owns t in [16i,16i+16); half = tid>>7 owns 32 m-chunks.
// Halves accumulate sequentially into ybuf. smem 44KB static.
// ---------------------------------------------------------------------------
__global__ __launch_bounds__(256) void conv_kernel(
    const float* __restrict__ u,   // (H,L)
    const float* __restrict__ D,   // (H,)
    float* __restrict__ y)         // (H,L)
{
    __shared__ ulonglong2 suq[1280];   // skewed float4 u blocks (20.0 KB)
    __shared__ ull k2e[1024];          // 8 KB
    __shared__ ull k2o[1024];          // 8 KB
    __shared__ float ybuf[Lc];         // 8 KB

    const int h   = blockIdx.x;
    const int tid = threadIdx.x;

    // ---- build swapped k-pair tables from transposed KlT (column h) ----
    // k[x] = g_KlT[x*Hc + h]; loads are L2-resident (KlT just written, 1MB)
    for (int p = tid; p < 1024; p += 256) {
        float ke = g_KlT[(2 * p) * Hc + h];                 // k[2p]
        float ko = g_KlT[(2 * p + 1) * Hc + h];             // k[2p+1]
        float km = p ? g_KlT[(2 * p - 1) * Hc + h] : 0.0f;  // k[2p-1]
        k2e[p] = pack2(ko, ke);                             // {k[2p+1], k[2p]}
        k2o[p] = pack2(ke, km);                             // {k[2p],  k[2p-1]}
    }

    // ---- fill skewed padded u (valid a in [1024, 3072)) ----
    const float4* ug4 = reinterpret_cast<const float4*>(u + h * Lc);
    for (int Q = tid; Q < 1024; Q += 256) {
        float4 v = make_float4(0.f, 0.f, 0.f, 0.f);
        if (Q >= 256 && Q < 768) v = ug4[Q - 256];
        ulonglong2 w;
        w.x = pack2(v.x, v.y);
        w.y = pack2(v.z, v.w);
        suq[Q + (Q >> 2)] = w;
    }
    __syncthreads();

    const int i    = tid & 127;        // output tile: t in [16i, 16i+16)
    const int half = tid >> 7;         // m-half: chunks [32*half, 32*half+32)

    ull accE[8], accO[8];
    #pragma unroll
    for (int j = 0; j < 8; ++j) { accE[j] = 0ULL; accO[j] = 0ULL; }

    int Q0 = 4 * i + 504 - 256 * half; // = 4i + 504 - 8c at c = 32*half
    const int pbase = 512 * half;      // p0 of first chunk

    #pragma unroll 1
    for (int cc = 0; cc < 32; ++cc) {
        ull W[24];
        const int base = Q0 + (Q0 >> 2);   // Q0 multiple of 4 -> exact skew
        #pragma unroll
        for (int b = 0; b < 12; ++b) {
            ulonglong2 v = suq[base + b + (b >> 2)];
            W[2 * b]     = v.x;
            W[2 * b + 1] = v.y;
        }
        const int p0 = pbase + 16 * cc;
        #pragma unroll
        for (int dp = 0; dp < 16; ++dp) {
            const ull kve = k2e[p0 + dp];
            #pragma unroll
            for (int j = 0; j < 8; ++j)
                ffma2(accE[j], kve, W[15 - dp + j]);
            const ull kvo = k2o[p0 + dp];
            #pragma unroll
            for (int j = 0; j < 8; ++j)
                ffma2(accO[j], kvo, W[16 - dp + j]);
        }
        Q0 -= 8;
    }

    // ---- sequential half accumulation into ybuf ----
    const float* suf = reinterpret_cast<const float*>(suq);

    if (half == 0) {
        const float dh = D[h];   // fold skip connection into half 0's write
        #pragma unroll
        for (int j = 0; j < 8; ++j) {
            const int tE = 16 * i + 2 * j;
            const int tO = tE + 1;
            int aE = tE + 1024, QE = aE >> 2;
            int aO = tO + 1024, QO = aO >> 2;
            float uE = suf[(QE + (QE >> 2)) * 4 + (aE & 3)];
            float uO = suf[(QO + (QO >> 2)) * 4 + (aO & 3)];
            ybuf[tE] = addpair(accE[j]) + dh * uE;
            ybuf[tO] = addpair(accO[j]) + dh * uO;
        }
    }
    __syncthreads();
    if (half == 1) {
        const float k2047 = lo32(k2e[1023]);   // k[2047]
        #pragma unroll
        for (int j = 0; j < 8; ++j) {
            const int tE = 16 * i + 2 * j;
            const int tO = tE + 1;
            ybuf[tE] += addpair(accE[j]);
            // fixup m = 2047 (odd outputs): u[tO - 1024] -> a = tO
            int a = tO, Q = a >> 2;
            ybuf[tO] += addpair(accO[j])
                      + k2047 * suf[(Q + (Q >> 2)) * 4 + (a & 3)];
        }
    }
    __syncthreads();

    // ---- coalesced store (256 float4 x2 = 2048 floats) ----
    {
        float4* yg4 = reinterpret_cast<float4*>(y + h * Lc);
        const float4* yb4 = reinterpret_cast<const float4*>(ybuf);
        yg4[tid]       = yb4[tid];
        yg4[tid + 256] = yb4[tid + 256];
    }
}

// ---------------------------------------------------------------------------
extern "C" void kernel_launch(void* const* d_in, const int* in_sizes, int n_in,
                              void* d_out, int out_size)
{
    const float* u = nullptr;
    const float* C = nullptr;
    const float* D = nullptr;
    const float* K = nullptr;
    for (int i = 0; i < n_in; ++i) {
        switch (in_sizes[i]) {
            case Hc * Lc:  u = (const float*)d_in[i]; break;
            case Hc * Nc:  C = (const float*)d_in[i]; break;
            case Hc:       D = (const float*)d_in[i]; break;
            default:
                if (in_sizes[i] == Lc * Hc * Nc) K = (const float*)d_in[i];
                break;
        }
    }

    float* y = (float*)d_out;

    kl_synth_kernel<<<Lc, 256>>>(K, C);   // one block per l, coalesced store
    conv_kernel<<<Hc, 256>>>(u, D, y);
}